// round 10
// baseline (speedup 1.0000x reference)
#include <cuda_runtime.h>
#include <cuda_bf16.h>
#include <stdint.h>

// PyramidROIAlign: output [B,N,7,7,256] f32, levels p2..p5 (256/128/64/32), NHWC.
// R10: R9's record-precompute + LDG.64 gathers.
//  L1tex model calibration: LDG.128 variants bind on within-instruction
//  wavefront replay (4 wf x 2.07 cyc), LDG.32 variants bind on the LSU
//  dispatch floor (1.82 cyc/instr). LDG.64 (2 wf/instr: 1 cross @1.0 + 1
//  within @2.07) minimizes max(wavefront, dispatch) -> ~60 cyc/sample.
//  setup: one thread per sample -> packed 16B record {off00|dx|lvl, off10, lx, ly}
//  main : one WARP per sample; 16x LDG.64 in 2 waves of 8; 2x STG.128 .cs.

#define POOLX 7
#define MAX_ROIS 8192

__device__ float4 g_srecs[MAX_ROIS * 49];

__global__ __launch_bounds__(256) void roi_setup_kernel(
    const float* __restrict__ boxes,   // [M,4]
    const float* __restrict__ meta,    // [B,93]
    int total, int N)
{
    int tid = blockIdx.x * blockDim.x + threadIdx.x;
    if (tid >= total) return;
    int pos = tid % 49;
    int roi = tid / 49;
    int b   = roi / N;
    int py  = pos / POOLX;
    int px  = pos - py * POOLX;

    float4 bx = __ldg(((const float4*)boxes) + roi);
    float y1 = bx.x, x1 = bx.y, y2 = bx.z, x2 = bx.w;
    float h = y2 - y1, w = x2 - x1;

    float area  = __ldg(meta + 4) * __ldg(meta + 5);
    float scale = sqrtf(fmaxf(h * w, 1e-12f));
    float rl    = log2f(scale * sqrtf(area) / 224.0f);
    int lvl = 4 + (int)rintf(rl);
    lvl = min(max(lvl, 2), 5);

    int H = 256 >> (lvl - 2);          // 256,128,64,32
    int W = H;

    float ty = (float)py * (1.0f / 6.0f);
    float tx = (float)px * (1.0f / 6.0f);
    float ys = (y1 + ty * h) * (float)(H - 1);
    float xs = (x1 + tx * w) * (float)(W - 1);

    float fy = floorf(ys), fx = floorf(xs);
    float ly = ys - fy,    lx = xs - fx;

    int y0  = min(max((int)fy,     0), H - 1);
    int y1i = min(max((int)fy + 1, 0), H - 1);
    int x0  = min(max((int)fx,     0), W - 1);
    int x1i = min(max((int)fx + 1, 0), W - 1);

    uint32_t off00 = (uint32_t)(((b * H + y0 ) * W + x0) * 64);  // float4 units, <2^23
    uint32_t off10 = (uint32_t)(((b * H + y1i) * W + x0) * 64);
    uint32_t dx    = (uint32_t)(x1i - x0);                       // 0 or 1

    float4 rec;
    rec.x = __uint_as_float(off00 | (dx << 23) | ((uint32_t)(lvl - 2) << 24));
    rec.y = __uint_as_float(off10);
    rec.z = lx;
    rec.w = ly;
    g_srecs[tid] = rec;
}

__global__ __launch_bounds__(256, 6) void roi_align_main_kernel(
    const float* __restrict__ p2,
    const float* __restrict__ p3,
    const float* __restrict__ p4,
    const float* __restrict__ p5,
    float* __restrict__ out,
    int totalWarps)
{
    int gw   = (blockIdx.x * blockDim.x + threadIdx.x) >> 5;
    int lane = threadIdx.x & 31;
    if (gw >= totalWarps) return;

    float4 rec = __ldg(&g_srecs[gw]);
    uint32_t a = __float_as_uint(rec.x);
    int o00f4 = (int)(a & 0x7FFFFFu);           // float4 units
    int dx    = (int)((a >> 23) & 1u);
    int lvl   = (int)(a >> 24);
    int o10f4 = (int)__float_as_uint(rec.y);
    float lx  = rec.z;
    float ly  = rec.w;

    const float* fp = (lvl == 0) ? p2 : (lvl == 1) ? p3 : (lvl == 2) ? p4 : p5;
    const float2* f2 = (const float2*)fp;

    float w11 = ly * lx;
    float w01 = lx - w11;            // lx*(1-ly)
    float w10 = ly - w11;            // ly*(1-lx)
    float w00 = 1.0f - lx - w10;     // (1-lx)*(1-ly)

    // float2 units: pixel = 128 float2. lane covers channels [2*lane, 2*lane+2)
    int o00 = o00f4 * 2 + lane;      // float2 index
    int o01 = o00 + dx * 128;
    int o10 = o10f4 * 2 + lane;
    int o11 = o10 + dx * 128;

    float2 ra0, ra1, rb0, rb1;       // accumulators: channels lane*2.., +64, +128, +192

    // ---- Wave 1: top corners, 8x LDG.64 ----
    {
        float2 t0 = __ldg(f2 + o00);
        float2 t1 = __ldg(f2 + o00 + 32);
        float2 t2 = __ldg(f2 + o00 + 64);
        float2 t3 = __ldg(f2 + o00 + 96);
        float2 u0 = __ldg(f2 + o01);
        float2 u1 = __ldg(f2 + o01 + 32);
        float2 u2 = __ldg(f2 + o01 + 64);
        float2 u3 = __ldg(f2 + o01 + 96);

        ra0.x = fmaf(u0.x, w01, t0.x * w00);
        ra0.y = fmaf(u0.y, w01, t0.y * w00);
        ra1.x = fmaf(u1.x, w01, t1.x * w00);
        ra1.y = fmaf(u1.y, w01, t1.y * w00);
        rb0.x = fmaf(u2.x, w01, t2.x * w00);
        rb0.y = fmaf(u2.y, w01, t2.y * w00);
        rb1.x = fmaf(u3.x, w01, t3.x * w00);
        rb1.y = fmaf(u3.y, w01, t3.y * w00);
    }
    // ---- Wave 2: bottom corners, 8x LDG.64 ----
    {
        float2 t0 = __ldg(f2 + o10);
        float2 t1 = __ldg(f2 + o10 + 32);
        float2 t2 = __ldg(f2 + o10 + 64);
        float2 t3 = __ldg(f2 + o10 + 96);
        float2 u0 = __ldg(f2 + o11);
        float2 u1 = __ldg(f2 + o11 + 32);
        float2 u2 = __ldg(f2 + o11 + 64);
        float2 u3 = __ldg(f2 + o11 + 96);

        ra0.x = fmaf(t0.x, w10, ra0.x); ra0.x = fmaf(u0.x, w11, ra0.x);
        ra0.y = fmaf(t0.y, w10, ra0.y); ra0.y = fmaf(u0.y, w11, ra0.y);
        ra1.x = fmaf(t1.x, w10, ra1.x); ra1.x = fmaf(u1.x, w11, ra1.x);
        ra1.y = fmaf(t1.y, w10, ra1.y); ra1.y = fmaf(u1.y, w11, ra1.y);
        rb0.x = fmaf(t2.x, w10, rb0.x); rb0.x = fmaf(u2.x, w11, rb0.x);
        rb0.y = fmaf(t2.y, w10, rb0.y); rb0.y = fmaf(u2.y, w11, rb0.y);
        rb1.x = fmaf(t3.x, w10, rb1.x); rb1.x = fmaf(u3.x, w11, rb1.x);
        rb1.y = fmaf(t3.y, w10, rb1.y); rb1.y = fmaf(u3.y, w11, rb1.y);
    }

    // Store: channels [2l,2l+2), [64+2l,..), [128+2l,..), [192+2l,..) as 4 STG.64 .cs
    float2* o2 = (float2*)out + (long)gw * 128 + lane;
    __stcs(o2,      ra0);
    __stcs(o2 + 32, ra1);
    __stcs(o2 + 64, rb0);
    __stcs(o2 + 96, rb1);
}

extern "C" void kernel_launch(void* const* d_in, const int* in_sizes, int n_in,
                              void* d_out, int out_size) {
    const float* boxes = (const float*)d_in[0];
    const float* meta  = (const float*)d_in[1];
    const float* p2    = (const float*)d_in[2];
    const float* p3    = (const float*)d_in[3];
    const float* p4    = (const float*)d_in[4];
    const float* p5    = (const float*)d_in[5];
    float* out = (float*)d_out;

    int B = in_sizes[1] / 93;              // image_meta [B,93]
    if (B <= 0) B = 2;
    int N = in_sizes[0] / (4 * B);         // boxes [B,N,4]
    int M = B * N;
    if (M > MAX_ROIS) M = MAX_ROIS;
    int total = M * 49;

    roi_setup_kernel<<<(total + 255) / 256, 256>>>(boxes, meta, total, N);

    int warpsPerBlock = 256 / 32;
    int blocks = (total + warpsPerBlock - 1) / warpsPerBlock;
    roi_align_main_kernel<<<blocks, 256>>>(p2, p3, p4, p5, out, total);
}

// round 11
// speedup vs baseline: 1.0485x; 1.0485x over previous
#include <cuda_runtime.h>
#include <cuda_bf16.h>

// PyramidROIAlign: output [B,N,7,7,256] f32, levels p2..p5 (256/128/64/32), NHWC.
// R11: row kernel (warp = (roi,py), 7 px cells unrolled, setup amortized 7x)
// + grid-stride persistent launch sized to fill the chip exactly
// (no wave-quantization tail), single fused kernel (min launch overhead).
// Memory per cell: 8x LDG.128 front-batched + 2x STG.128 streaming (.cs).
// We are at the LTS (~5KB/sample) wall; this round removes overhead/tail.

#define POOLX 7
#define C4N 64   // 256 ch / 4

__global__ __launch_bounds__(256, 4) void roi_align_persist_kernel(
    const float* __restrict__ boxes,   // [M,4]  (y1,x1,y2,x2)
    const float* __restrict__ meta,    // [B,93]
    const float* __restrict__ p2,
    const float* __restrict__ p3,
    const float* __restrict__ p4,
    const float* __restrict__ p5,
    float* __restrict__ out,
    int totalRowWarps, int N)
{
    int lane      = threadIdx.x & 31;
    int warpInGrid = (blockIdx.x * blockDim.x + threadIdx.x) >> 5;
    int warpStride = (gridDim.x * blockDim.x) >> 5;

    for (int gw = warpInGrid; gw < totalRowWarps; gw += warpStride) {
        int py  = gw % POOLX;
        int roi = gw / POOLX;
        int b   = roi / N;

        // ---- per-(roi,py) setup, once per 7 cells ----
        float4 bx = __ldg(((const float4*)boxes) + roi);
        float y1 = bx.x, x1 = bx.y, y2 = bx.z, x2 = bx.w;
        float h = y2 - y1, w = x2 - x1;

        float area  = __ldg(meta + 4) * __ldg(meta + 5);
        float scale = sqrtf(fmaxf(h * w, 1e-12f));
        float rl    = log2f(scale * sqrtf(area) / 224.0f);
        int lvl = 4 + (int)rintf(rl);
        lvl = min(max(lvl, 2), 5);

        const float* fmap;
        int H;
        if      (lvl == 2) { fmap = p2; H = 256; }
        else if (lvl == 3) { fmap = p3; H = 128; }
        else if (lvl == 4) { fmap = p4; H = 64;  }
        else               { fmap = p5; H = 32;  }
        const int W = H;

        float ty = (float)py * (1.0f / 6.0f);
        float ys = (y1 + ty * h) * (float)(H - 1);
        float fy = floorf(ys);
        float ly = ys - fy;
        int y0  = min(max((int)fy,     0), H - 1);
        int y1i = min(max((int)fy + 1, 0), H - 1);

        int rowT = (b * H + y0 ) * W;
        int rowB = (b * H + y1i) * W;

        float xsc = x1 * (float)(W - 1);
        float xst = w * (float)(W - 1) * (1.0f / 6.0f);

        const float4* f4 = (const float4*)fmap;
        float4* obase = (float4*)out + (long)gw * (POOLX * C4N) + lane;

        #pragma unroll
        for (int px = 0; px < POOLX; px++) {
            float xs = fmaf((float)px, xst, xsc);
            float fx = floorf(xs);
            float lx = xs - fx;
            int x0  = min(max((int)fx,     0), W - 1);
            int x1i = min(max((int)fx + 1, 0), W - 1);

            float w11 = ly * lx;
            float w01 = lx - w11;              // lx*(1-ly)
            float w10 = ly - w11;              // ly*(1-lx)
            float w00 = 1.0f - lx - w10;       // (1-lx)*(1-ly)

            int o00 = (rowT + x0 ) * C4N + lane;
            int o01 = (rowT + x1i) * C4N + lane;
            int o10 = (rowB + x0 ) * C4N + lane;
            int o11 = (rowB + x1i) * C4N + lane;

            float4 a00 = __ldg(f4 + o00);
            float4 a01 = __ldg(f4 + o01);
            float4 a10 = __ldg(f4 + o10);
            float4 a11 = __ldg(f4 + o11);
            float4 b00 = __ldg(f4 + o00 + 32);
            float4 b01 = __ldg(f4 + o01 + 32);
            float4 b10 = __ldg(f4 + o10 + 32);
            float4 b11 = __ldg(f4 + o11 + 32);

            float4 ra, rb;
            ra.x = fmaf(a01.x, w01, a00.x * w00);
            ra.y = fmaf(a01.y, w01, a00.y * w00);
            ra.z = fmaf(a01.z, w01, a00.z * w00);
            ra.w = fmaf(a01.w, w01, a00.w * w00);
            ra.x = fmaf(a10.x, w10, ra.x); ra.x = fmaf(a11.x, w11, ra.x);
            ra.y = fmaf(a10.y, w10, ra.y); ra.y = fmaf(a11.y, w11, ra.y);
            ra.z = fmaf(a10.z, w10, ra.z); ra.z = fmaf(a11.z, w11, ra.z);
            ra.w = fmaf(a10.w, w10, ra.w); ra.w = fmaf(a11.w, w11, ra.w);

            rb.x = fmaf(b01.x, w01, b00.x * w00);
            rb.y = fmaf(b01.y, w01, b00.y * w00);
            rb.z = fmaf(b01.z, w01, b00.z * w00);
            rb.w = fmaf(b01.w, w01, b00.w * w00);
            rb.x = fmaf(b10.x, w10, rb.x); rb.x = fmaf(b11.x, w11, rb.x);
            rb.y = fmaf(b10.y, w10, rb.y); rb.y = fmaf(b11.y, w11, rb.y);
            rb.z = fmaf(b10.z, w10, rb.z); rb.z = fmaf(b11.z, w11, rb.z);
            rb.w = fmaf(b10.w, w10, rb.w); rb.w = fmaf(b11.w, w11, rb.w);

            __stcs(obase + px * C4N,      ra);
            __stcs(obase + px * C4N + 32, rb);
        }
    }
}

extern "C" void kernel_launch(void* const* d_in, const int* in_sizes, int n_in,
                              void* d_out, int out_size) {
    const float* boxes = (const float*)d_in[0];
    const float* meta  = (const float*)d_in[1];
    const float* p2    = (const float*)d_in[2];
    const float* p3    = (const float*)d_in[3];
    const float* p4    = (const float*)d_in[4];
    const float* p5    = (const float*)d_in[5];
    float* out = (float*)d_out;

    int B = in_sizes[1] / 93;              // image_meta [B,93]
    if (B <= 0) B = 2;
    int N = in_sizes[0] / (4 * B);         // boxes [B,N,4]
    int M = B * N;
    int totalRowWarps = M * POOLX;         // one warp-task per (roi, py)

    // Persistent grid: fill the chip exactly (148 SMs x 4 blocks @ 256 thr, 64 regs)
    int blocks = 148 * 4;
    int maxBlocks = (totalRowWarps + 7) / 8;   // don't overshoot tiny workloads
    if (blocks > maxBlocks) blocks = maxBlocks;
    roi_align_persist_kernel<<<blocks, 256>>>(boxes, meta, p2, p3, p4, p5, out,
                                              totalRowWarps, N);
}